// round 17
// baseline (speedup 1.0000x reference)
#include <cuda_runtime.h>
#include <cuda_fp16.h>

// Problem constants (fixed by the dataset)
#define NMAX 100000
#define EMAX 1600000
#define D    64
#define G    64
#define VMAX 64

// ---- device scratch (no allocations allowed) ----
__device__ int   g_degi  [NMAX];        // in-degree (real edges only)
__device__ float g_dinv  [NMAX];        // rsqrt(deg+1)
__device__ uint2 g_nd    [NMAX];        // packed {node_type, dinv bits}
__device__ int   g_off   [NMAX + 1];    // CSR row offsets (by destination)
__device__ int   g_cursor[NMAX];        // build cursors
__device__ int   g_bsum  [256];         // scan block partials
__device__ int   g_csrc  [EMAX];        // CSR: source node per edge slot
__device__ unsigned int g_H1h [VMAX * 32]; // H1 = emb@W1, fp16 packed (64 halves/row)
__device__ float g_bufA  [NMAX * D];
__device__ uint4 g_hs    [NMAX * 8];    // hs = (x@W)*dinv, fp16 (layers 2,3)
__device__ float g_bufC  [NMAX * D];
__device__ float g_pool  [G * D];
__device__ float g_cnt   [G];

// ------------------------------------------------------------------
// K_htab: H1[v] = emb[v] @ W1, stored fp16-packed. One block per v, 64 threads.
// ------------------------------------------------------------------
__global__ void k_htab(const float* __restrict__ emb, const float* __restrict__ W) {
    int v = blockIdx.x;
    int d = threadIdx.x;
    __shared__ float se[D];
    __shared__ float sacc[D];
    se[d] = emb[v * D + d];
    __syncthreads();
    float acc = 0.0f;
#pragma unroll
    for (int k = 0; k < D; k++)
        acc = fmaf(se[k], W[k * D + d], acc);
    sacc[d] = acc;
    __syncthreads();
    if (d < 32) {
        __half2 h = __floats2half2_rn(sacc[d * 2], sacc[d * 2 + 1]);
        g_H1h[v * 32 + d] = *(unsigned int*)&h;
    }
}

// ------------------------------------------------------------------
// K_hist: in-degree histogram over edge targets (col)
// ------------------------------------------------------------------
__global__ void k_hist(const int* __restrict__ col, int E) {
    int e = blockIdx.x * blockDim.x + threadIdx.x;
    if (e < E) atomicAdd(&g_degi[col[e]], 1);
}

// ------------------------------------------------------------------
// Scan pass 1: per-block (1024 elems) exclusive scan of g_degi -> g_off,
//   block totals -> g_bsum. Also dinv = rsqrt(deg+1) and packed g_nd.
// ------------------------------------------------------------------
__global__ void k_scan1(const int* __restrict__ nt, int N) {
    __shared__ int sh[256];
    int t = threadIdx.x;
    int base = blockIdx.x * 1024;
    int v[4];
    int sum = 0;
#pragma unroll
    for (int j = 0; j < 4; j++) {
        int idx = base + t * 4 + j;
        v[j] = (idx < N) ? g_degi[idx] : 0;
        if (idx < N) {
            float di = rsqrtf((float)(v[j] + 1));
            g_dinv[idx] = di;
            g_nd[idx] = make_uint2((unsigned int)nt[idx], __float_as_uint(di));
        }
        sum += v[j];
    }
    sh[t] = sum;
    __syncthreads();
    for (int o = 1; o < 256; o <<= 1) {
        int x = (t >= o) ? sh[t - o] : 0;
        __syncthreads();
        sh[t] += x;
        __syncthreads();
    }
    int excl = sh[t] - sum;
    if (t == 255) g_bsum[blockIdx.x] = sh[255];
    int run = excl;
#pragma unroll
    for (int j = 0; j < 4; j++) {
        int idx = base + t * 4 + j;
        if (idx < N) g_off[idx] = run;
        run += v[j];
    }
}

// ------------------------------------------------------------------
// Scan pass 2: single block exclusive-scans the block partials (B <= 256)
// ------------------------------------------------------------------
__global__ void k_scan2(int B) {
    __shared__ int sh[256];
    int t = threadIdx.x;
    int v = (t < B) ? g_bsum[t] : 0;
    sh[t] = v;
    __syncthreads();
    for (int o = 1; o < 256; o <<= 1) {
        int x = (t >= o) ? sh[t - o] : 0;
        __syncthreads();
        sh[t] += x;
        __syncthreads();
    }
    if (t < B) g_bsum[t] = sh[t] - v;
}

// ------------------------------------------------------------------
// Scan pass 3: add block base, init cursors, set sentinel off[N]=E
// ------------------------------------------------------------------
__global__ void k_scan3(int N, int E) {
    int i = blockIdx.x * blockDim.x + threadIdx.x;
    if (i < N) {
        int o = g_off[i] + g_bsum[i >> 10];
        g_off[i]    = o;
        g_cursor[i] = o;
    }
    if (i == 0) g_off[N] = E;
}

// ------------------------------------------------------------------
// K_build: fill CSR source array via per-destination cursors
// ------------------------------------------------------------------
__global__ void k_build(const int* __restrict__ row, const int* __restrict__ col, int E) {
    int e = blockIdx.x * blockDim.x + threadIdx.x;
    if (e < E) {
        int p = atomicAdd(&g_cursor[col[e]], 1);
        g_csrc[p] = row[e];
    }
}

// ------------------------------------------------------------------
// K_agg1: layer-1 aggregation WITHOUT materialized hs.
//   hs[s] = H1[nt[s]] * dinv[s]; H1 (fp16, 30 rows) staged in smem.
//   Per edge: one broadcast 8B g_nd load + one LDS.128 from the table.
//   warp per node, 8 lanes/edge (g = lane>>3, sub = lane&7).
// ------------------------------------------------------------------
__global__ void __launch_bounds__(256)
k_agg1(const float* __restrict__ b, float* __restrict__ y, int N, int V) {
    __shared__ uint4 sH[VMAX * 8];      // fp16 table, 128B per row
    int tid = threadIdx.x;
    const uint4* H1 = (const uint4*)g_H1h;
    for (int i = tid; i < V * 8; i += 256) sH[i] = H1[i];
    __syncthreads();

    int w    = (blockIdx.x * blockDim.x + tid) >> 5;
    int lane = tid & 31;
    if (w >= N) return;
    int g   = lane >> 3;
    int sub = lane & 7;

    int i   = g_off[w];
    int end = g_off[w + 1];

    uint2 nds = g_nd[w];
    float di  = __uint_as_float(nds.y);
    uint4 self = sH[nds.x * 8 + sub];

    float acc[8];
#pragma unroll
    for (int k = 0; k < 8; k++) acc[k] = 0.f;

    // main loop: 4 edges per iteration (1 per group)
    for (; i + 4 <= end; i += 4) {
        int s = __ldg(&g_csrc[i + g]);
        uint2 nd = __ldg(&g_nd[s]);
        float ds = __uint_as_float(nd.y);
        uint4 p  = sH[nd.x * 8 + sub];
        float2 f;
        f = __half22float2(*(__half2*)&p.x); acc[0] = fmaf(f.x, ds, acc[0]); acc[1] = fmaf(f.y, ds, acc[1]);
        f = __half22float2(*(__half2*)&p.y); acc[2] = fmaf(f.x, ds, acc[2]); acc[3] = fmaf(f.y, ds, acc[3]);
        f = __half22float2(*(__half2*)&p.z); acc[4] = fmaf(f.x, ds, acc[4]); acc[5] = fmaf(f.y, ds, acc[5]);
        f = __half22float2(*(__half2*)&p.w); acc[6] = fmaf(f.x, ds, acc[6]); acc[7] = fmaf(f.y, ds, acc[7]);
    }
    // tail (up to 3 edges), predicated per group
    {
        int idx = i + g;
        if (idx < end) {
            int s = __ldg(&g_csrc[idx]);
            uint2 nd = __ldg(&g_nd[s]);
            float ds = __uint_as_float(nd.y);
            uint4 p  = sH[nd.x * 8 + sub];
            float2 f;
            f = __half22float2(*(__half2*)&p.x); acc[0] = fmaf(f.x, ds, acc[0]); acc[1] = fmaf(f.y, ds, acc[1]);
            f = __half22float2(*(__half2*)&p.y); acc[2] = fmaf(f.x, ds, acc[2]); acc[3] = fmaf(f.y, ds, acc[3]);
            f = __half22float2(*(__half2*)&p.z); acc[4] = fmaf(f.x, ds, acc[4]); acc[5] = fmaf(f.y, ds, acc[5]);
            f = __half22float2(*(__half2*)&p.w); acc[6] = fmaf(f.x, ds, acc[6]); acc[7] = fmaf(f.y, ds, acc[7]);
        }
    }

    // combine the 4 edge-groups
#pragma unroll
    for (int k = 0; k < 8; k++) {
        acc[k] += __shfl_xor_sync(0xFFFFFFFFu, acc[k], 8);
        acc[k] += __shfl_xor_sync(0xFFFFFFFFu, acc[k], 16);
    }

    // self-loop term: H1[nt[w]] * dinv[w]
    {
        float2 f;
        f = __half22float2(*(__half2*)&self.x); acc[0] = fmaf(f.x, di, acc[0]); acc[1] = fmaf(f.y, di, acc[1]);
        f = __half22float2(*(__half2*)&self.y); acc[2] = fmaf(f.x, di, acc[2]); acc[3] = fmaf(f.y, di, acc[3]);
        f = __half22float2(*(__half2*)&self.z); acc[4] = fmaf(f.x, di, acc[4]); acc[5] = fmaf(f.y, di, acc[5]);
        f = __half22float2(*(__half2*)&self.w); acc[6] = fmaf(f.x, di, acc[6]); acc[7] = fmaf(f.y, di, acc[7]);
    }

    if (g < 2) {
        float4 bv = ((const float4*)b)[sub * 2 + g];
        int k0 = g * 4;
        float4 o;
        o.x = bv.x + di * acc[k0 + 0];
        o.y = bv.y + di * acc[k0 + 1];
        o.z = bv.z + di * acc[k0 + 2];
        o.w = bv.w + di * acc[k0 + 3];
        ((float4*)y)[(long long)w * 16 + sub * 2 + g] = o;
    }
}

// ------------------------------------------------------------------
// K_mm v4: hs = fp16( (relu?(x) @ W) * dinv )   (layers 2,3)
// ------------------------------------------------------------------
__global__ void __launch_bounds__(256)
k_mm(const float* __restrict__ x,
     const float* __restrict__ W,
     uint2* __restrict__ hs,
     int N, int relu_in) {
    __shared__ float4 sW4[D * 16];       // [k][dq]      16 KB
    __shared__ float4 sx4[128 * 16];     // [row][kq]    32 KB
    int tid = threadIdx.x;
    const float4* W4 = (const float4*)W;
    for (int i = tid; i < D * 16; i += 256) sW4[i] = W4[i];

    int base = blockIdx.x * 128;
    for (int t4 = tid; t4 < 128 * 16; t4 += 256) {
        int r  = t4 >> 4;
        int kq = t4 & 15;
        int n  = base + r;
        float4 v = make_float4(0.f, 0.f, 0.f, 0.f);
        if (n < N) {
            v = ((const float4*)x)[(long long)n * 16 + kq];
            if (relu_in) {
                v.x = fmaxf(v.x, 0.f); v.y = fmaxf(v.y, 0.f);
                v.z = fmaxf(v.z, 0.f); v.w = fmaxf(v.w, 0.f);
            }
        }
        sx4[t4] = v;
    }
    __syncthreads();

    int dq = tid & 15;
    int rg = tid >> 4;
    int n0 = base + rg * 8;

    float4 a[8];
#pragma unroll
    for (int r = 0; r < 8; r++) a[r] = make_float4(0.f, 0.f, 0.f, 0.f);

#pragma unroll
    for (int kq = 0; kq < 16; kq++) {
        float4 w0 = sW4[(kq * 4 + 0) * 16 + dq];
        float4 w1 = sW4[(kq * 4 + 1) * 16 + dq];
        float4 w2 = sW4[(kq * 4 + 2) * 16 + dq];
        float4 w3 = sW4[(kq * 4 + 3) * 16 + dq];
#pragma unroll
        for (int r = 0; r < 8; r++) {
            float4 xv = sx4[(rg * 8 + r) * 16 + kq];
            a[r].x = fmaf(xv.x, w0.x, a[r].x); a[r].y = fmaf(xv.x, w0.y, a[r].y);
            a[r].z = fmaf(xv.x, w0.z, a[r].z); a[r].w = fmaf(xv.x, w0.w, a[r].w);
            a[r].x = fmaf(xv.y, w1.x, a[r].x); a[r].y = fmaf(xv.y, w1.y, a[r].y);
            a[r].z = fmaf(xv.y, w1.z, a[r].z); a[r].w = fmaf(xv.y, w1.w, a[r].w);
            a[r].x = fmaf(xv.z, w2.x, a[r].x); a[r].y = fmaf(xv.z, w2.y, a[r].y);
            a[r].z = fmaf(xv.z, w2.z, a[r].z); a[r].w = fmaf(xv.z, w2.w, a[r].w);
            a[r].x = fmaf(xv.w, w3.x, a[r].x); a[r].y = fmaf(xv.w, w3.y, a[r].y);
            a[r].z = fmaf(xv.w, w3.z, a[r].z); a[r].w = fmaf(xv.w, w3.w, a[r].w);
        }
    }

#pragma unroll
    for (int r = 0; r < 8; r++) {
        int n = n0 + r;
        if (n < N) {
            float di = g_dinv[n];
            __half2 h0 = __floats2half2_rn(a[r].x * di, a[r].y * di);
            __half2 h1 = __floats2half2_rn(a[r].z * di, a[r].w * di);
            uint2 st;
            st.x = *(unsigned int*)&h0;
            st.y = *(unsigned int*)&h1;
            hs[(long long)n * 16 + dq] = st;
        }
    }
}

// ------------------------------------------------------------------
// K_agg v5: y[n] = b + dinv[n] * ( sum hs[src] + hs[n] )   (layers 2,3)
// ------------------------------------------------------------------
__global__ void __launch_bounds__(256)
k_agg(const uint4* __restrict__ hs, const float* __restrict__ b,
      float* __restrict__ y, int N) {
    int w    = (blockIdx.x * blockDim.x + threadIdx.x) >> 5;
    int lane = threadIdx.x & 31;
    if (w >= N) return;
    int g   = lane >> 3;
    int sub = lane & 7;

    int i   = g_off[w];
    int end = g_off[w + 1];

    float di   = g_dinv[w];
    uint4 self = hs[(long long)w * 8 + sub];

    float acc[8];
#pragma unroll
    for (int k = 0; k < 8; k++) acc[k] = 0.f;

    for (; i + 8 <= end; i += 8) {
        int s0 = __ldg(&g_csrc[i + g]);
        int s1 = __ldg(&g_csrc[i + 4 + g]);
        uint4 p0 = hs[(long long)s0 * 8 + sub];
        uint4 p1 = hs[(long long)s1 * 8 + sub];
        __half2 t0 = __hadd2(*(__half2*)&p0.x, *(__half2*)&p1.x);
        __half2 t1 = __hadd2(*(__half2*)&p0.y, *(__half2*)&p1.y);
        __half2 t2 = __hadd2(*(__half2*)&p0.z, *(__half2*)&p1.z);
        __half2 t3 = __hadd2(*(__half2*)&p0.w, *(__half2*)&p1.w);
        float2 f;
        f = __half22float2(t0); acc[0] += f.x; acc[1] += f.y;
        f = __half22float2(t1); acc[2] += f.x; acc[3] += f.y;
        f = __half22float2(t2); acc[4] += f.x; acc[5] += f.y;
        f = __half22float2(t3); acc[6] += f.x; acc[7] += f.y;
    }
    for (; i < end; i += 4) {
        int idx = i + g;
        if (idx < end) {
            int s = __ldg(&g_csrc[idx]);
            uint4 p = hs[(long long)s * 8 + sub];
            float2 f;
            f = __half22float2(*(__half2*)&p.x); acc[0] += f.x; acc[1] += f.y;
            f = __half22float2(*(__half2*)&p.y); acc[2] += f.x; acc[3] += f.y;
            f = __half22float2(*(__half2*)&p.z); acc[4] += f.x; acc[5] += f.y;
            f = __half22float2(*(__half2*)&p.w); acc[6] += f.x; acc[7] += f.y;
        }
    }

#pragma unroll
    for (int k = 0; k < 8; k++) {
        acc[k] += __shfl_xor_sync(0xFFFFFFFFu, acc[k], 8);
        acc[k] += __shfl_xor_sync(0xFFFFFFFFu, acc[k], 16);
    }

    {
        float2 f;
        f = __half22float2(*(__half2*)&self.x); acc[0] += f.x; acc[1] += f.y;
        f = __half22float2(*(__half2*)&self.y); acc[2] += f.x; acc[3] += f.y;
        f = __half22float2(*(__half2*)&self.z); acc[4] += f.x; acc[5] += f.y;
        f = __half22float2(*(__half2*)&self.w); acc[6] += f.x; acc[7] += f.y;
    }

    if (g < 2) {
        float4 bv = ((const float4*)b)[sub * 2 + g];
        int k0 = g * 4;
        float4 o;
        o.x = bv.x + di * acc[k0 + 0];
        o.y = bv.y + di * acc[k0 + 1];
        o.z = bv.z + di * acc[k0 + 2];
        o.w = bv.w + di * acc[k0 + 3];
        ((float4*)y)[(long long)w * 16 + sub * 2 + g] = o;
    }
}

// ------------------------------------------------------------------
// K_pool v2: segment mean accumulation. CHUNK=32 nodes/block,
//   4-wide unrolled loads. batch sorted -> register-accumulate.
// ------------------------------------------------------------------
#define POOL_CHUNK 32

#define POOL_STEP(bg, v)                                    \
    do {                                                    \
        if ((bg) != cur) {                                  \
            if (cur >= 0) {                                 \
                atomicAdd(&g_pool[cur * D + d], acc);       \
                if (d == 0) atomicAdd(&g_cnt[cur], cnt);    \
            }                                               \
            cur = (bg); acc = 0.f; cnt = 0.f;               \
        }                                                   \
        acc += (v); cnt += 1.f;                             \
    } while (0)

__global__ void k_pool(const float* __restrict__ x, const int* __restrict__ batch, int N) {
    int d = threadIdx.x;
    int s = blockIdx.x * POOL_CHUNK;
    int eN = min(s + POOL_CHUNK, N);
    float acc = 0.0f, cnt = 0.0f;
    int cur = -1;
    int n = s;
    for (; n + 4 <= eN; n += 4) {
        int b0 = batch[n],     b1 = batch[n + 1];
        int b2 = batch[n + 2], b3 = batch[n + 3];
        float v0 = x[(long long)n * D + d];
        float v1 = x[(long long)(n + 1) * D + d];
        float v2 = x[(long long)(n + 2) * D + d];
        float v3 = x[(long long)(n + 3) * D + d];
        POOL_STEP(b0, v0);
        POOL_STEP(b1, v1);
        POOL_STEP(b2, v2);
        POOL_STEP(b3, v3);
    }
    for (; n < eN; n++) {
        int bg = batch[n];
        float v = x[(long long)n * D + d];
        POOL_STEP(bg, v);
    }
    if (cur >= 0) {
        atomicAdd(&g_pool[cur * D + d], acc);
        if (d == 0) atomicAdd(&g_cnt[cur], cnt);
    }
}

// ------------------------------------------------------------------
// K_final: pooled = sum/max(cnt,1); out = pooled / ||pooled||_2
// ------------------------------------------------------------------
__global__ void k_final(float* __restrict__ out) {
    int r    = blockIdx.x * 32 + (threadIdx.x >> 5);
    int lane = threadIdx.x & 31;
    float c  = fmaxf(g_cnt[r], 1.0f);
    float v0 = g_pool[r * D + lane]      / c;
    float v1 = g_pool[r * D + 32 + lane] / c;
    float ss = v0 * v0 + v1 * v1;
#pragma unroll
    for (int o = 16; o > 0; o >>= 1) ss += __shfl_xor_sync(0xFFFFFFFFu, ss, o);
    float inv = rsqrtf(ss);
    out[r * D + lane]      = v0 * inv;
    out[r * D + 32 + lane] = v1 * inv;
}

// ------------------------------------------------------------------
// Host launcher
// ------------------------------------------------------------------
extern "C" void kernel_launch(void* const* d_in, const int* in_sizes, int n_in,
                              void* d_out, int out_size) {
    const int*   node_types = (const int*)  d_in[0];
    const int*   edge_index = (const int*)  d_in[1];
    const int*   batch      = (const int*)  d_in[2];
    const float* emb_table  = (const float*)d_in[3];
    const float* W1 = (const float*)d_in[4];
    const float* b1 = (const float*)d_in[5];
    const float* W2 = (const float*)d_in[6];
    const float* b2 = (const float*)d_in[7];
    const float* W3 = (const float*)d_in[8];
    const float* b3 = (const float*)d_in[9];
    float* out = (float*)d_out;

    const int N = in_sizes[0];
    const int E = in_sizes[1] / 2;
    const int V = in_sizes[3] / D;
    const int* row = edge_index;        // edge_index[0, :]
    const int* col = edge_index + E;    // edge_index[1, :]

    float* bufA; cudaGetSymbolAddress((void**)&bufA, g_bufA);
    uint4* hsB;  cudaGetSymbolAddress((void**)&hsB,  g_hs);
    float* bufC; cudaGetSymbolAddress((void**)&bufC, g_bufC);
    int*   degi; cudaGetSymbolAddress((void**)&degi, g_degi);
    float* pool; cudaGetSymbolAddress((void**)&pool, g_pool);
    float* cnt;  cudaGetSymbolAddress((void**)&cnt,  g_cnt);

    const int T = 256;
    const int scanB = (N + 1023) / 1024;

    cudaMemsetAsync(degi, 0, N * sizeof(int));
    cudaMemsetAsync(pool, 0, G * D * sizeof(float));
    cudaMemsetAsync(cnt,  0, G * sizeof(float));

    int mm_blocks  = (N + 127) / 128;
    int agg_blocks = (N + 7) / 8;       // 8 warps/block, warp per node

    // ---- precompute: degrees/dinv/nd, CSR, H1 table ----
    k_htab <<<V, 64>>>(emb_table, W1);                                    // 1
    k_hist <<<(E + T - 1) / T, T>>>(col, E);                              // 2
    k_scan1<<<scanB, 256>>>(node_types, N);                               // 3
    k_scan2<<<1, 256>>>(scanB);                                           // 4
    k_scan3<<<(N + T - 1) / T, T>>>(N, E);                                // 5
    k_build<<<(E + T - 1) / T, T>>>(row, col, E);                         // 6

    // layer 1: fused table aggregation (no materialized hs, no hs1 kernel)
    k_agg1<<<agg_blocks, T>>>(b1, bufC, N, V);
    // layer 2
    k_mm <<<mm_blocks, T>>>(bufC, W2, (uint2*)hsB, N, 1);
    k_agg<<<agg_blocks, T>>>(hsB, b2, bufA, N);
    // layer 3
    k_mm <<<mm_blocks, T>>>(bufA, W3, (uint2*)hsB, N, 1);
    k_agg<<<agg_blocks, T>>>(hsB, b3, bufC, N);

    // mean-pool + L2 normalize
    k_pool <<<(N + POOL_CHUNK - 1) / POOL_CHUNK, 64>>>(bufC, batch, N);
    k_final<<<2, 1024>>>(out);
}